// round 16
// baseline (speedup 1.0000x reference)
#include <cuda_runtime.h>
#include <cuda_fp16.h>
#include <cstdint>
#include <cstddef>

#define NROWS 16384

// ---------------- scratch (device globals: no allocations allowed) -------------
// "A-format" (fp16): row-major; within each 64-col k-group, cols permuted:
//   blk=(c>>4)&3, q=c&15, h=q>>3, rem=q&7, t=rem>>1, b=rem&1
//   newc = (c&~63) | (blk<<4) | (t<<2) | (h<<1) | b
// "B-format" (fp16): per 64-k tile: [16 r][N n][4 halves], r=blk*4+t.
__device__ __align__(16) __half g_G   [(size_t)NROWS * 1536];  // A-format [H1 | gamma]
__device__ __align__(16) __half g_AB  [(size_t)NROWS * 4096];  // plain row-major fp16
__device__ __align__(16) __half g_H   [(size_t)NROWS * 2048];  // A-format
__device__ __align__(16) __half g_W2a [(size_t)512  * 1024];   // W2, A-format
__device__ __align__(16) __half g_Wcat[(size_t)1024 * 4096];   // W3cat, B-format
__device__ __align__(16) __half g_W3p [(size_t)1536 * 4096];   // GEMM2 B: kt0..7=W23, kt8..23=gamma rows
__device__ __align__(16) __half g_W4p [(size_t)2048 * 1024];   // B-format
__device__ float g_bias3[4096];                                // b2 @ W3cat

// ---------------- helpers ----------------

__device__ __forceinline__ int apermc(int c) {  // A-format column permutation
    int blk = (c >> 4) & 3;
    int q   = c & 15;
    int h = q >> 3, rem = q & 7, t = rem >> 1, b = rem & 1;
    return (c & ~63) | (blk << 4) | (t << 2) | (h << 1) | b;
}

__device__ __forceinline__ uint32_t smem_u32(const void* p) {
    uint32_t a;
    asm("{ .reg .u64 t; cvta.to.shared.u64 t, %1; cvt.u32.u64 %0, t; }" : "=r"(a) : "l"(p));
    return a;
}
__device__ __forceinline__ void cp_async16(uint32_t saddr, const void* g) {
    asm volatile("cp.async.cg.shared.global [%0], [%1], 16;" :: "r"(saddr), "l"(g));
}
__device__ __forceinline__ void cp_commit() {
    asm volatile("cp.async.commit_group;" ::: "memory");
}
template<int N> __device__ __forceinline__ void cp_wait() {
    asm volatile("cp.async.wait_group %0;" :: "n"(N) : "memory");
}

// m16n8k16 fp16 -> fp32 acc
__device__ __forceinline__ void mma_f16(float d[4], uint2 ag, uint2 ag8, uint2 b) {
    asm volatile(
        "mma.sync.aligned.m16n8k16.row.col.f32.f16.f16.f32 "
        "{%0,%1,%2,%3}, {%4,%5,%6,%7}, {%8,%9}, {%0,%1,%2,%3};\n"
        : "+f"(d[0]), "+f"(d[1]), "+f"(d[2]), "+f"(d[3])
        : "r"(ag.x), "r"(ag8.x), "r"(ag.y), "r"(ag8.y), "r"(b.x), "r"(b.y));
}

// ---------------- packing: weights + bias row (one launch) ----------------
// roles by blockIdx.x:
//  [0,512):      W2 row m -> g_W2a (A-format)
//  [512,1536):   W3cat row k -> g_Wcat (B-format, N=4096)
//  [1536,2560):  gamma row j -> g_W3p rows 512+j (B-format, N=4096)
//  [2560,4608):  W4 row k -> g_W4p (B-format, N=1024)
//  [4608,4624):  bias3[n] = sum_j b2[j]*W3cat[j][n]
__global__ void pack_weights(const float* __restrict__ W2,
                             const float* __restrict__ W3,
                             const float* __restrict__ W4,
                             const float* __restrict__ b2) {
    int bid = blockIdx.x;
    if (bid < 512) {
        int m = bid;
        const float* src = W2 + (size_t)m * 1024;
        __half* dst = g_W2a + (size_t)m * 1024;
        for (int c = threadIdx.x; c < 1024; c += blockDim.x)
            dst[apermc(c)] = __float2half_rn(src[c]);
        return;
    }
    if (bid >= 4608) {
        int n = (bid - 4608) * 256 + threadIdx.x;
        float acc = 0.0f;
        if (n < 2048) {
#pragma unroll 4
            for (int j = 0; j < 1024; j++) acc = fmaf(b2[j], W3[(size_t)j * 2048 + n], acc);
        } else {
#pragma unroll 4
            for (int j = 0; j < 1024; j++) acc = fmaf(b2[j], W3[(size_t)(2048 + j) * 2048 + (n - 2048)], acc);
        }
        g_bias3[n] = acc;
        return;
    }
    // B-format rows
    const float *src0, *src1;
    __half* dstbase;
    int k, N;
    if (bid < 1536) {          // W3cat row k (K-dim of W23 GEMM)
        k = bid - 512; N = 4096; dstbase = g_Wcat;
        src0 = W3 + (size_t)k * 2048;
        src1 = W3 + (size_t)(2048 + k) * 2048;
    } else if (bid < 2560) {   // gamma rows of GEMM2 B: global k2 = 512 + j
        int j = bid - 1536; N = 4096; dstbase = g_W3p;
        src0 = W3 + (size_t)(1024 + j) * 2048;
        src1 = W3 + (size_t)(3072 + j) * 2048;
        k = 512 + j;
    } else {                   // W4 row
        k = bid - 2560; N = 1024; dstbase = g_W4p;
        src0 = W4 + (size_t)k * 1024;
        src1 = nullptr;
    }
    int kt = k >> 6, kk = k & 63;
    int blk = kk >> 4, q = kk & 15;
    int h = q >> 3, rem = q & 7, t = rem >> 1, b = rem & 1;
    int r = blk * 4 + t;
    __half* dst = dstbase + ((size_t)(kt * 16 + r) * N) * 4 + h * 2 + b;
    for (int n = threadIdx.x; n < N; n += blockDim.x) {
        float v = (src1 && n >= 2048) ? src1[n - 2048] : src0[n];
        dst[(size_t)n * 4] = __float2half_rn(v);
    }
}

// ---------------- front: H1 + gamma -> g_G [16384 x 1536] A-format --------------
__global__ void front_kernel(const float* __restrict__ pos,
                             const float* __restrict__ W1,
                             const float* __restrict__ b1) {
    int k = blockIdx.x;
    int j = threadIdx.x;  // 512
    __half* row = g_G + (size_t)k * 1536;
    // H1 part (cols 0..511)
    float p0 = pos[3 * k + 0], p1 = pos[3 * k + 1], p2 = pos[3 * k + 2];
    float v = b1[j];
    v = fmaf(p0, W1[j], v);
    v = fmaf(p1, W1[512 + j], v);
    v = fmaf(p2, W1[1024 + j], v);
    row[apermc(j)] = __float2half_rn(fmaxf(v, 0.0f));
    // gamma part (cols 512..1535), i = j
    double denom = exp(-(2.0 * (double)j / 1024.0) * 9.210340371976184);
    double ang = (double)k * denom;
    const double INV2PI = 0.15915494309189533577;
    const double TWOPI  = 6.2831853071795864769;
    double rr = ang - floor(ang * INV2PI) * TWOPI;
    float s, c;
    sincosf((float)rr, &s, &c);
    int nc = apermc(512 + 2 * j);   // even col -> (nc, nc+1) contiguous
    *reinterpret_cast<__half2*>(row + nc) = __floats2half2_rn(s, c);
}

// ---------------- combine: H = relu(AB[k,0:2048] + AB[p,2048:4096] + b3) --------
__global__ void combine_kernel(const int* __restrict__ parent,
                               const float* __restrict__ b3) {
    int k = blockIdx.x;
    int t = threadIdx.x;  // 512 threads, 4 cols each
    int p = parent[k];
    int c4 = 4 * t;
    const __half2* a2  = reinterpret_cast<const __half2*>(g_AB + (size_t)k * 4096 + c4);
    const __half2* b2h = reinterpret_cast<const __half2*>(g_AB + (size_t)p * 4096 + 2048 + c4);
    float2 a01 = __half22float2(a2[0]),  a23 = __half22float2(a2[1]);
    float2 p01 = __half22float2(b2h[0]), p23 = __half22float2(b2h[1]);
    const float4 bb = *reinterpret_cast<const float4*>(b3 + c4);
    __half* row = g_H + (size_t)k * 2048;
    int base = apermc(c4);  // cols map to base, base+1, base+4, base+5
    *reinterpret_cast<__half2*>(row + base) =
        __floats2half2_rn(fmaxf(a01.x + p01.x + bb.x, 0.0f),
                          fmaxf(a01.y + p01.y + bb.y, 0.0f));
    *reinterpret_cast<__half2*>(row + base + 4) =
        __floats2half2_rn(fmaxf(a23.x + p23.x + bb.z, 0.0f),
                          fmaxf(a23.y + p23.y + bb.w, 0.0f));
}

// ---------------- FP16 GEMM (mma.sync m16n8k16, cp.async 3-stage) --------------
// CTA tile 128x128, k-tile 64. 256 threads (8 warps 2Mx4N, warp tile 64x32).
// 2 CTAs/SM. outmode 0: fp32 row-major. 1: A-format fp16. 2: fp16 row-major.
// 3: B-format fp16 (ldc = N of the B-operand being produced).

#define STAGES      3
#define SA_BYTES    (128 * 160)
#define SB_BYTES    (16 * 1056)
#define STAGE_BYTES (SA_BYTES + SB_BYTES)
#define GEMM_SMEM   (STAGES * STAGE_BYTES)   // 112128

__global__ __launch_bounds__(256, 2)
void gemm_f16(const __half* __restrict__ A, int lda,
              const __half* __restrict__ B, int ldbN,
              float* __restrict__ Cf, int ldc,
              __half* __restrict__ Ch,
              int Kd,
              const float* __restrict__ bias, int outmode) {
    extern __shared__ char smem[];
    const uint32_t uA = smem_u32(smem);
    const uint32_t uB = uA + STAGES * SA_BYTES;

    const int tid  = threadIdx.x;
    const int lane = tid & 31;
    const int wid  = tid >> 5;
    const int g    = lane >> 2;
    const int tig  = lane & 3;
    const int wm   = wid & 1;
    const int wn   = wid >> 1;

    const int blockM = blockIdx.y << 7;
    const int blockN = blockIdx.x << 7;

    float acc[4][4][4];
#pragma unroll
    for (int i = 0; i < 4; i++)
#pragma unroll
        for (int j = 0; j < 4; j++)
#pragma unroll
            for (int c = 0; c < 4; c++)
                acc[i][j][c] = 0.0f;

    int aRow[4], aOff[4], bR[4], bSeg[4];
#pragma unroll
    for (int i = 0; i < 4; i++) {
        int l = tid + (i << 8);
        aRow[i] = l >> 3;
        aOff[i] = l & 7;
        bR[i]   = l >> 6;
        bSeg[i] = l & 63;
    }

    const int tiles = Kd >> 6;

    auto issue = [&](int kt, int s) {
        const int koff = kt << 6;
#pragma unroll
        for (int i = 0; i < 4; i++) {
            cp_async16(uA + (uint32_t)(s * SA_BYTES + aRow[i] * 160 + aOff[i] * 16),
                       A + (size_t)(blockM + aRow[i]) * lda + koff + aOff[i] * 8);
            cp_async16(uB + (uint32_t)(s * SB_BYTES + bR[i] * 1056 + bSeg[i] * 16),
                       B + ((size_t)(kt * 16 + bR[i]) * ldbN + blockN + bSeg[i] * 2) * 4);
        }
    };

    issue(0, 0); cp_commit();
    issue(1, 1); cp_commit();

    for (int kt = 0; kt < tiles; kt++) {
        cp_wait<1>();
        __syncthreads();
        {
            int nk = kt + 2;
            if (nk < tiles) issue(nk, nk % STAGES);
            cp_commit();
        }

        const int buf = kt % STAGES;
        const uint2* cA = reinterpret_cast<const uint2*>(smem + buf * SA_BYTES);
        const uint2* cB = reinterpret_cast<const uint2*>(smem + STAGES * SA_BYTES + buf * SB_BYTES);

#pragma unroll
        for (int ks = 0; ks < 4; ks++) {
            uint2 ag[4], ag8[4], bf[4];
#pragma unroll
            for (int mt = 0; mt < 4; mt++) {
                int m0 = (wm << 6) + (mt << 4) + g;
                int idx = m0 * 20 + (ks << 2) + tig;
                ag[mt]  = cA[idx];
                ag8[mt] = cA[idx + 8 * 20];
            }
#pragma unroll
            for (int nt = 0; nt < 4; nt++) {
                int n0 = (wn << 5) + (nt << 3) + g;
                bf[nt] = cB[((ks << 2) + tig) * 132 + n0];
            }
#pragma unroll
            for (int mt = 0; mt < 4; mt++)
#pragma unroll
                for (int nt = 0; nt < 4; nt++)
                    mma_f16(acc[mt][nt], ag[mt], ag8[mt], bf[nt]);
        }
    }

    // ---------------- epilogue ----------------
#pragma unroll
    for (int mt = 0; mt < 4; mt++) {
#pragma unroll
        for (int nt = 0; nt < 4; nt++) {
            int row = blockM + (wm << 6) + (mt << 4) + g;
            int col = blockN + (wn << 5) + (nt << 3) + (tig << 1);
            float bv0 = 0.0f, bv1 = 0.0f;
            if (bias) { bv0 = bias[col]; bv1 = bias[col + 1]; }
            float o0 = acc[mt][nt][0] + bv0;
            float o1 = acc[mt][nt][1] + bv1;
            float o2 = acc[mt][nt][2] + bv0;
            float o3 = acc[mt][nt][3] + bv1;
            if (outmode == 0) {
                float2 v0; v0.x = o0; v0.y = o1;
                float2 v1; v1.x = o2; v1.y = o3;
                *reinterpret_cast<float2*>(Cf + (size_t)row * ldc + col)       = v0;
                *reinterpret_cast<float2*>(Cf + (size_t)(row + 8) * ldc + col) = v1;
            } else if (outmode == 1) {
                int nc = apermc(col);
                *reinterpret_cast<__half2*>(Ch + (size_t)row * ldc + nc)       = __floats2half2_rn(o0, o1);
                *reinterpret_cast<__half2*>(Ch + (size_t)(row + 8) * ldc + nc) = __floats2half2_rn(o2, o3);
            } else if (outmode == 2) {
                *reinterpret_cast<__half2*>(Ch + (size_t)row * ldc + col)       = __floats2half2_rn(o0, o1);
                *reinterpret_cast<__half2*>(Ch + (size_t)(row + 8) * ldc + col) = __floats2half2_rn(o2, o3);
            } else {
                // B-format store: produced matrix is a B-operand with N = ldc, k = row
                int kk = row & 63, ktr = row >> 6;
                int blk = kk >> 4, q = kk & 15;
                int h = q >> 3, rem = q & 7, tq = rem >> 1, bq = rem & 1;
                int r = blk * 4 + tq;
                size_t base = ((size_t)(ktr * 16 + r) * ldc + col) * 4 + h * 2 + bq;
                Ch[base]     = __float2half_rn(o0);   // (row,   col)
                Ch[base + 4] = __float2half_rn(o1);   // (row,   col+1)
                Ch[base + 2] = __float2half_rn(o2);   // (row+8, col)   : h flips
                Ch[base + 6] = __float2half_rn(o3);   // (row+8, col+1)
            }
        }
    }
}

// ---------------- launch ----------------

extern "C" void kernel_launch(void* const* d_in, const int* in_sizes, int n_in,
                              void* d_out, int out_size) {
    const float* pos    = (const float*)d_in[0];
    const int*   parent = (const int*)d_in[1];
    const float* W1 = (const float*)d_in[2];
    const float* b1 = (const float*)d_in[3];
    const float* W2 = (const float*)d_in[4];
    const float* b2 = (const float*)d_in[5];
    const float* W3 = (const float*)d_in[6];
    const float* b3 = (const float*)d_in[7];
    const float* W4 = (const float*)d_in[8];
    const float* b4 = (const float*)d_in[9];
    float* out = (float*)d_out;

    __half *pG, *pABh, *pH, *pW2a, *pWcat, *pW3p, *pW4p;
    float* pBias3;
    cudaGetSymbolAddress((void**)&pG,    g_G);
    cudaGetSymbolAddress((void**)&pABh,  g_AB);
    cudaGetSymbolAddress((void**)&pH,    g_H);
    cudaGetSymbolAddress((void**)&pW2a,  g_W2a);
    cudaGetSymbolAddress((void**)&pWcat, g_Wcat);
    cudaGetSymbolAddress((void**)&pW3p,  g_W3p);
    cudaGetSymbolAddress((void**)&pW4p,  g_W4p);
    cudaGetSymbolAddress((void**)&pBias3, g_bias3);
    cudaFuncSetAttribute(gemm_f16, cudaFuncAttributeMaxDynamicSharedMemorySize, GEMM_SMEM);

    // 0: pack all weights + bias3 (W2a, Wcat, W3p-gamma rows, W4p, b2@W3cat)
    pack_weights<<<4624, 256>>>(W2, W3, W4, b2);
    // 1: front: g_G = [H1 | gamma]  (A-format, 1536 wide)
    front_kernel<<<NROWS, 512>>>(pos, W1, b1);
    // 2: W23 = W2 @ W3cat -> g_W3p rows 0..511 (B-format out)  [512,1024]x[1024,4096]
    gemm_f16<<<dim3(32, 4), 256, GEMM_SMEM>>>(pW2a, 1024, pWcat, 4096,
                                              nullptr, 4096, pW3p, 1024, nullptr, 3);
    // 3: GEMM2: AB = [H1|gamma] @ [W23; W3gamma] + bias3  [16384,1536]x[1536,4096] -> fp16
    gemm_f16<<<dim3(32, 128), 256, GEMM_SMEM>>>(pG, 1536, pW3p, 4096,
                                                nullptr, 4096, pABh, 1536, pBias3, 2);
    // 4: combine -> g_H (A-format fp16)
    combine_kernel<<<NROWS, 512>>>(parent, b3);
    // 5: GEMM3: out = H @ W4 + b4 -> fp32 plain  [16384,2048]x[2048,1024]
    gemm_f16<<<dim3(8, 128), 256, GEMM_SMEM>>>(pH, 2048, pW4p, 1024,
                                               out, 1024, nullptr, 2048, b4, 0);
}